// round 12
// baseline (speedup 1.0000x reference)
#include <cuda_runtime.h>
#include <cuda_bf16.h>
#include <cstdint>
#include <math.h>

// Problem sizes
#define T_ 256
#define B_ 128
#define D_ 1024
#define H_ 1024
#define O_ 1024
#define MROWS (T_*B_)   // 32768
#define NCOLS (4*H_)    // 4096

// ---------------- device scratch (static, zero-init, no allocs) -------------
__device__ __align__(16) __nv_bfloat16 g_xbf[(size_t)MROWS * D_];        // 64MB
__device__ __align__(16) float         g_Zx[(size_t)MROWS * NCOLS];      // 512MB
__device__ __align__(16) uint2         g_Wxp[32u*64u*16u*32u];           // 8MB  [cn][kt][nt][lane]
__device__ __align__(16) uint2         g_Whp[128u*64u*4u*32u];           // 8MB  [ct][kt][g][lane]
__device__ float                       g_b4[NCOLS];
__device__ __align__(16) __nv_bfloat16 g_h[2][B_*H_];                    // ping-pong h (bf16)
__device__ __align__(16) float         g_c[B_*H_];                       // cell state fp32
__device__ __align__(16) float         g_hT[B_*H_];                      // final h fp32

// ---------------- small PTX helpers ----------------
__device__ __forceinline__ void cpa16(uint32_t saddr, const void* gptr) {
    asm volatile("cp.async.cg.shared.global [%0], [%1], 16;" :: "r"(saddr), "l"(gptr));
}
__device__ __forceinline__ void cpa_commit() { asm volatile("cp.async.commit_group;"); }
__device__ __forceinline__ void cpa_wait0()  { asm volatile("cp.async.wait_group 0;"); }
__device__ __forceinline__ void cpa_wait1()  { asm volatile("cp.async.wait_group 1;"); }

__device__ __forceinline__ void pdl_trigger() {
    asm volatile("griddepcontrol.launch_dependents;" ::: "memory");
}
__device__ __forceinline__ void pdl_wait() {
    asm volatile("griddepcontrol.wait;" ::: "memory");
}

__device__ __forceinline__ void ldsm_x4(uint32_t& r0, uint32_t& r1, uint32_t& r2, uint32_t& r3,
                                        uint32_t saddr) {
    asm volatile("ldmatrix.sync.aligned.m8n8.x4.shared.b16 {%0,%1,%2,%3}, [%4];"
                 : "=r"(r0), "=r"(r1), "=r"(r2), "=r"(r3) : "r"(saddr));
}
__device__ __forceinline__ void mma16816(float* d, const uint32_t* a, const uint2 b) {
    asm volatile("mma.sync.aligned.m16n8k16.row.col.f32.bf16.bf16.f32 "
                 "{%0,%1,%2,%3}, {%4,%5,%6,%7}, {%8,%9}, {%0,%1,%2,%3};"
                 : "+f"(d[0]), "+f"(d[1]), "+f"(d[2]), "+f"(d[3])
                 : "r"(a[0]), "r"(a[1]), "r"(a[2]), "r"(a[3]), "r"(b.x), "r"(b.y));
}
__device__ __forceinline__ uint32_t s2u(const void* p) {
    return (uint32_t)__cvta_generic_to_shared(p);
}
__device__ __forceinline__ uint32_t swz(uint32_t byte) {   // 128B swizzle
    return byte ^ ((byte >> 3) & 0x70u);
}
__device__ __forceinline__ float fast_sigmoid(float x) {
    return 1.f / (1.f + __expf(-x));
}
__device__ __forceinline__ float fast_tanh(float x) {
    float e = __expf(-2.f * fabsf(x));
    float t = (1.f - e) / (1.f + e);
    return copysignf(t, x);
}

// ---------------- prep kernel 1: pack_wh + pack_b ----------
__global__ void __launch_bounds__(256) k_prep_w(const float* Wf, const float* bf,
                                                const float* Wi, const float* bi,
                                                const float* Wg, const float* bg,
                                                const float* Wo, const float* bo) {
    unsigned blk = blockIdx.x, tid = threadIdx.x;
    if (blk < 4096u) {
        unsigned id = blk * 256u + tid;       // pack Wh fragments
        unsigned lane = id & 31u, g = (id >> 5) & 3u, kt = (id >> 7) & 63u, ct = id >> 13;
        unsigned j = ct * 8u + (lane >> 2);
        unsigned k0 = kt * 16u + (lane & 3u) * 2u;
        const float* W = (g == 0) ? Wf : (g == 1) ? Wi : (g == 2) ? Wg : Wo;
        const float* base = W + (size_t)j * (D_ + H_) + D_ + k0;
        __nv_bfloat162 p0 = __floats2bfloat162_rn(base[0], base[1]);
        __nv_bfloat162 p1 = __floats2bfloat162_rn(base[8], base[9]);
        uint2 out;
        out.x = *reinterpret_cast<uint32_t*>(&p0);
        out.y = *reinterpret_cast<uint32_t*>(&p1);
        g_Whp[id] = out;
    } else {
        for (int r = 0; r < 16; r++) {
            unsigned i = tid * 16u + r;
            unsigned g = i >> 10, j = i & 1023u;
            const float* b = (g == 0) ? bf : (g == 1) ? bi : (g == 2) ? bg : bo;
            g_b4[i] = b[j];
        }
    }
}

// ---------------- prep kernel 2: cvt_x + pack_wx ----------------
__global__ void __launch_bounds__(512) k_prep_x(const float* __restrict__ x,
                                                const float* Wf, const float* Wi,
                                                const float* Wg, const float* Wo) {
    unsigned blk = blockIdx.x, tid = threadIdx.x;
    if (blk < 16384u) {
        size_t idx = (size_t)blk * 512 + tid;   // 8388608 float4s
        float4 v = reinterpret_cast<const float4*>(x)[idx];
        __nv_bfloat162* dst = reinterpret_cast<__nv_bfloat162*>(g_xbf);
        dst[idx * 2 + 0] = __floats2bfloat162_rn(v.x, v.y);
        dst[idx * 2 + 1] = __floats2bfloat162_rn(v.z, v.w);
    } else {
        unsigned id = (blk - 16384u) * 512u + tid;   // 1048576 ids
        unsigned lane = id & 31u, nt = (id >> 5) & 15u, kt = (id >> 9) & 63u, cn = id >> 15;
        unsigned c = cn * 128u + nt * 8u + (lane >> 2);
        unsigned g = c >> 10, j = c & 1023u;
        unsigned k0 = kt * 16u + (lane & 3u) * 2u;
        const float* W = (g == 0) ? Wf : (g == 1) ? Wi : (g == 2) ? Wg : Wo;
        const float* base = W + (size_t)j * (D_ + H_) + k0;
        __nv_bfloat162 p0 = __floats2bfloat162_rn(base[0], base[1]);
        __nv_bfloat162 p1 = __floats2bfloat162_rn(base[8], base[9]);
        uint2 out;
        out.x = *reinterpret_cast<uint32_t*>(&p0);
        out.y = *reinterpret_cast<uint32_t*>(&p1);
        g_Wxp[id] = out;
    }
}

// ---------------- Phase A: Zx = xbf @ Wx4^T + b4 ----------------
__global__ void __launch_bounds__(256) k_gemmA() {
    extern __shared__ char sm[];
    const int tid = threadIdx.x, lane = tid & 31, w = tid >> 5;
    const int wm = w >> 2, wn = w & 3;
    const int cn = blockIdx.x;           // 0..31
    const int m0 = blockIdx.y * 128;     // 0..32640

    float acc[4][4][4];
#pragma unroll
    for (int a = 0; a < 4; a++)
#pragma unroll
        for (int b = 0; b < 4; b++)
#pragma unroll
            for (int c = 0; c < 4; c++) acc[a][b][c] = 0.f;

    auto load_chunk = [&](int kc) {
        int st = kc % 3;
        char* A = sm + (size_t)st * 32768;
        uint4* bdst = reinterpret_cast<uint4*>(sm + (size_t)st * 32768 + 16384);
#pragma unroll
        for (int i = 0; i < 4; i++) {
            int idx = tid + i * 256;
            int row = idx >> 3, seg = idx & 7;
            const void* src = &g_xbf[(size_t)(m0 + row) * D_ + kc * 64 + seg * 8];
            cpa16(s2u(A + swz(row * 128 + seg * 16)), src);
        }
        const uint4* bsrc = reinterpret_cast<const uint4*>(&g_Wxp[((size_t)cn * 64 + kc * 4) * 16 * 32]);
#pragma unroll
        for (int i = 0; i < 4; i++) {
            int idx = tid + i * 256;
            cpa16(s2u(bdst + idx), bsrc + idx);
        }
        cpa_commit();
    };

    load_chunk(0);
    load_chunk(1);
    for (int kc = 0; kc < 16; kc++) {
        if (kc < 15) cpa_wait1(); else cpa_wait0();
        __syncthreads();
        int st = kc % 3;
        char* A = sm + (size_t)st * 32768;
        uint2* Bsm = reinterpret_cast<uint2*>(sm + (size_t)st * 32768 + 16384);
#pragma unroll
        for (int ktl = 0; ktl < 4; ktl++) {
            uint32_t afr[4][4];
#pragma unroll
            for (int mt = 0; mt < 4; mt++) {
                int r = wm * 64 + mt * 16 + (lane & 15);
                int ch = ktl * 16 + ((lane >> 4) << 3);
                ldsm_x4(afr[mt][0], afr[mt][1], afr[mt][2], afr[mt][3],
                        s2u(A + swz(r * 128 + ch * 2)));
            }
            uint2 bfr[4];
#pragma unroll
            for (int nt = 0; nt < 4; nt++)
                bfr[nt] = Bsm[((ktl) * 16 + wn * 4 + nt) * 32 + lane];
#pragma unroll
            for (int mt = 0; mt < 4; mt++)
#pragma unroll
                for (int nt = 0; nt < 4; nt++)
                    mma16816(acc[mt][nt], afr[mt], bfr[nt]);
        }
        if (kc + 2 < 16) load_chunk(kc + 2);
    }
#pragma unroll
    for (int mt = 0; mt < 4; mt++) {
        int r0 = m0 + wm * 64 + mt * 16 + (lane >> 2);
#pragma unroll
        for (int nt = 0; nt < 4; nt++) {
            int c0 = cn * 128 + wn * 32 + nt * 8 + (lane & 3) * 2;
            float b0 = g_b4[c0], b1 = g_b4[c0 + 1];
            float2 v0 = make_float2(acc[mt][nt][0] + b0, acc[mt][nt][1] + b1);
            float2 v1 = make_float2(acc[mt][nt][2] + b0, acc[mt][nt][3] + b1);
            *reinterpret_cast<float2*>(&g_Zx[(size_t)r0 * NCOLS + c0]) = v0;
            *reinterpret_cast<float2*>(&g_Zx[(size_t)(r0 + 8) * NCOLS + c0]) = v1;
        }
    }
}

// ---------------- Phase B: one kernel per timestep with PDL overlap ---------
// 128 CTAs x 256 threads. CTA ct owns hidden units [ct*8, ct*8+8) x 4 gates
// x 128 batches. Pre-sync phase (Zx float4 loads + Wh cp.async) overlaps the
// previous step via programmatic dependent launch; griddepcontrol.wait guards
// the h/c-dependent phase. smem: WhS 64KB + ring 2x16KB + zs 16KB = 112KB
// (2 consecutive grids co-resident per SM).
__global__ void __launch_bounds__(256) k_step(int t) {
    extern __shared__ char sm[];
    uint2* WhS = reinterpret_cast<uint2*>(sm);                 // 64KB
    char*  As  = sm + 65536;                                    // 2 x 16KB ring
    float* zs  = reinterpret_cast<float*>(sm + 65536 + 32768);  // 16KB
    const int ct = blockIdx.x;
    const int tid = threadIdx.x, lane = tid & 31, w = tid >> 5;
    const int wm = w >> 1, wn = w & 1;
    const bool last = (t == T_ - 1);
    const int bb = tid >> 1;              // batch row (2 threads per batch)
    const int jl = (tid & 1) * 4;         // 4 consecutive units per thread

    pdl_trigger();   // all CTAs resident -> next step's grid may launch

    float zx[4][4];  // zx[i][g] for cells jl..jl+3
    float cst[4];

    if (t == 0) {
        pdl_wait();   // Zx written by k_gemmA (predecessor)
        const float* zp = &g_Zx[(size_t)bb * NCOLS + ct * 8 + jl];
#pragma unroll
        for (int g = 0; g < 4; g++) {
            float4 v = *reinterpret_cast<const float4*>(zp + g * 1024);
            zx[0][g] = v.x; zx[1][g] = v.y; zx[2][g] = v.z; zx[3][g] = v.w;
        }
#pragma unroll
        for (int i = 0; i < 4; i++) cst[i] = 0.f;
    } else {
        // ---- pre-sync phase: independent of step t-1 ----
        {
            const uint4* src = reinterpret_cast<const uint4*>(&g_Whp[(size_t)ct * 64 * 4 * 32]);
#pragma unroll
            for (int i = 0; i < 16; i++) {
                int idx = tid + i * 256;
                cpa16(s2u(reinterpret_cast<uint4*>(WhS) + idx), src + idx);
            }
            cpa_commit();
        }
        {
            const float* zp = &g_Zx[(size_t)(t * B_ + bb) * NCOLS + ct * 8 + jl];
#pragma unroll
            for (int g = 0; g < 4; g++) {
                float4 v = __ldcs(reinterpret_cast<const float4*>(zp + g * 1024));
                zx[0][g] = v.x; zx[1][g] = v.y; zx[2][g] = v.z; zx[3][g] = v.w;
            }
        }

        pdl_wait();   // step t-1 fully complete: h(t-1), c(t-1) visible

        {
            float4 cv = *reinterpret_cast<const float4*>(&g_c[(size_t)bb * H_ + ct * 8 + jl]);
            cst[0] = cv.x; cst[1] = cv.y; cst[2] = cv.z; cst[3] = cv.w;
        }

        const __nv_bfloat16* hsrc = g_h[(t + 1) & 1];
        auto load_chunk = [&](int kc) {
            char* A = As + (size_t)(kc & 1) * 16384;
#pragma unroll
            for (int i = 0; i < 4; i++) {
                int idx = tid + i * 256;
                int row = idx >> 3, seg = idx & 7;
                const void* src = &hsrc[(size_t)row * H_ + kc * 64 + seg * 8];
                cpa16(s2u(A + swz(row * 128 + seg * 16)), src);
            }
            cpa_commit();
        };
        load_chunk(0);
        load_chunk(1);

        float acc[2][2][4];
#pragma unroll
        for (int a = 0; a < 2; a++)
#pragma unroll
            for (int b = 0; b < 2; b++)
#pragma unroll
                for (int c = 0; c < 4; c++) acc[a][b][c] = 0.f;

        for (int kc = 0; kc < 16; kc++) {
            if (kc < 15) cpa_wait1(); else cpa_wait0();
            __syncthreads();           // chunk kc visible to all
            char* A = As + (size_t)(kc & 1) * 16384;
#pragma unroll
            for (int ktl = 0; ktl < 4; ktl++) {
                uint2 bfr[2];
#pragma unroll
                for (int nt = 0; nt < 2; nt++)
                    bfr[nt] = WhS[(((kc * 4 + ktl) * 4) + wn * 2 + nt) * 32 + lane];
#pragma unroll
                for (int mt = 0; mt < 2; mt++) {
                    int r = wm * 32 + mt * 16 + (lane & 15);
                    int ch = ktl * 16 + ((lane >> 4) << 3);
                    uint32_t afr[4];
                    ldsm_x4(afr[0], afr[1], afr[2], afr[3],
                            s2u(A + swz(r * 128 + ch * 2)));
                    mma16816(acc[mt][0], afr, bfr[0]);
                    mma16816(acc[mt][1], afr, bfr[1]);
                }
            }
            __syncthreads();           // all reads of buffer (kc&1) done
            if (kc + 2 < 16) load_chunk(kc + 2);
        }
        // z exchange via smem
#pragma unroll
        for (int mt = 0; mt < 2; mt++) {
            int r = wm * 32 + mt * 16 + (lane >> 2);
#pragma unroll
            for (int nt = 0; nt < 2; nt++) {
                int cl = (wn * 2 + nt) * 8 + (lane & 3) * 2;
                zs[r * 32 + cl]           = acc[mt][nt][0];
                zs[r * 32 + cl + 1]       = acc[mt][nt][1];
                zs[(r + 8) * 32 + cl]     = acc[mt][nt][2];
                zs[(r + 8) * 32 + cl + 1] = acc[mt][nt][3];
            }
        }
        __syncthreads();
    }

    // gate math + h/c write (4 consecutive cells per thread)
    __nv_bfloat16* hdst = g_h[t & 1];
    float hh[4], cn[4];
#pragma unroll
    for (int i = 0; i < 4; i++) {
        float zi = zx[i][0], zf = zx[i][1], zg = zx[i][2], zo = zx[i][3];
        if (t > 0) {
            int o = bb * 32 + jl + i;
            zi += zs[o + 0];
            zf += zs[o + 8];
            zg += zs[o + 16];
            zo += zs[o + 24];
        }
        float it = fast_sigmoid(zi);
        float ft = fast_sigmoid(zf);
        float gt = fast_tanh(zg);
        float ot = fast_sigmoid(zo);
        cn[i] = ft * cst[i] + it * gt;
        hh[i] = ot * fast_tanh(cn[i]);
    }
    if (!last) {
        __nv_bfloat162 h01 = __floats2bfloat162_rn(hh[0], hh[1]);
        __nv_bfloat162 h23 = __floats2bfloat162_rn(hh[2], hh[3]);
        uint2 hp;
        hp.x = *reinterpret_cast<uint32_t*>(&h01);
        hp.y = *reinterpret_cast<uint32_t*>(&h23);
        *reinterpret_cast<uint2*>(&hdst[(size_t)bb * H_ + ct * 8 + jl]) = hp;
        *reinterpret_cast<float4*>(&g_c[(size_t)bb * H_ + ct * 8 + jl]) =
            make_float4(cn[0], cn[1], cn[2], cn[3]);
    } else {
        *reinterpret_cast<float4*>(&g_hT[(size_t)bb * H_ + ct * 8 + jl]) =
            make_float4(hh[0], hh[1], hh[2], hh[3]);
    }
}

// ---------------- Phase C: logits + log_softmax ----------------
__global__ void __launch_bounds__(256) k_logits(const float* __restrict__ Wout,
                                                const float* __restrict__ bout,
                                                float* __restrict__ out) {
    __shared__ float hs[1024];
    __shared__ float ls[1024];
    __shared__ float red[16];
    const int b = blockIdx.x, tid = threadIdx.x, lane = tid & 31, w = tid >> 5;
    for (int i = tid; i < 1024; i += 256) hs[i] = g_hT[(size_t)b * H_ + i];
    __syncthreads();
    for (int k = 0; k < 4; k++) {
        int o = tid + k * 256;
        const float4* wr = reinterpret_cast<const float4*>(Wout + (size_t)o * H_);
        float s = 0.f;
#pragma unroll 4
        for (int h4 = 0; h4 < 256; h4++) {
            float4 wv = wr[h4];
            s += hs[h4 * 4 + 0] * wv.x + hs[h4 * 4 + 1] * wv.y +
                 hs[h4 * 4 + 2] * wv.z + hs[h4 * 4 + 3] * wv.w;
        }
        ls[o] = s + bout[o];
    }
    __syncthreads();
    float lm = -1e30f;
    for (int i = tid; i < 1024; i += 256) lm = fmaxf(lm, ls[i]);
#pragma unroll
    for (int off = 16; off; off >>= 1) lm = fmaxf(lm, __shfl_xor_sync(0xffffffffu, lm, off));
    if (lane == 0) red[w] = lm;
    __syncthreads();
    float m = red[0];
#pragma unroll
    for (int j = 1; j < 8; j++) m = fmaxf(m, red[j]);
    float se = 0.f;
    for (int i = tid; i < 1024; i += 256) se += expf(ls[i] - m);
#pragma unroll
    for (int off = 16; off; off >>= 1) se += __shfl_xor_sync(0xffffffffu, se, off);
    if (lane == 0) red[8 + w] = se;
    __syncthreads();
    float tot = 0.f;
#pragma unroll
    for (int j = 0; j < 8; j++) tot += red[8 + j];
    float lse = logf(tot);
    for (int i = tid; i < 1024; i += 256)
        out[(size_t)b * O_ + i] = ls[i] - m - lse;
}

// ---------------- launch ----------------
extern "C" void kernel_launch(void* const* d_in, const int* in_sizes, int n_in,
                              void* d_out, int out_size) {
    const float* x    = (const float*)d_in[0];
    const float* Wf   = (const float*)d_in[1];
    const float* bf   = (const float*)d_in[2];
    const float* Wi   = (const float*)d_in[3];
    const float* bi   = (const float*)d_in[4];
    const float* Wg   = (const float*)d_in[5];
    const float* bg   = (const float*)d_in[6];
    const float* Wo   = (const float*)d_in[7];
    const float* bo   = (const float*)d_in[8];
    const float* Wout = (const float*)d_in[9];
    const float* bout = (const float*)d_in[10];
    float* out = (float*)d_out;

    cudaFuncSetAttribute(k_gemmA, cudaFuncAttributeMaxDynamicSharedMemorySize, 98304);
    cudaFuncSetAttribute(k_step,  cudaFuncAttributeMaxDynamicSharedMemorySize, 114688);

    k_prep_w<<<4097, 256>>>(Wf, bf, Wi, bi, Wg, bg, Wo, bo);
    k_prep_x<<<18432, 512>>>(x, Wf, Wi, Wg, Wo);
    dim3 gA(32, 256);
    k_gemmA<<<gA, 256, 98304>>>();

    // per-step kernels with programmatic dependent launch
    cudaLaunchConfig_t cfg = {};
    cfg.gridDim = dim3(128, 1, 1);
    cfg.blockDim = dim3(256, 1, 1);
    cfg.dynamicSmemBytes = 114688;
    cfg.stream = 0;
    cudaLaunchAttribute attrs[1];
    attrs[0].id = cudaLaunchAttributeProgrammaticStreamSerialization;
    attrs[0].val.programmaticStreamSerializationAllowed = 1;
    cfg.attrs = attrs;
    cfg.numAttrs = 1;
    for (int t = 0; t < T_; t++)
        cudaLaunchKernelEx(&cfg, k_step, t);

    k_logits<<<B_, 256>>>(Wout, bout, out);
}

// round 13
// speedup vs baseline: 1.3545x; 1.3545x over previous
#include <cuda_runtime.h>
#include <cuda_bf16.h>
#include <cstdint>
#include <math.h>

// Problem sizes
#define T_ 256
#define B_ 128
#define D_ 1024
#define H_ 1024
#define O_ 1024
#define MROWS (T_*B_)   // 32768
#define NCOLS (4*H_)    // 4096

// ---------------- device scratch (static, zero-init, no allocs) -------------
__device__ __align__(16) __nv_bfloat16 g_xbf[(size_t)MROWS * D_];        // 64MB
__device__ __align__(16) float         g_Zx[(size_t)MROWS * NCOLS];      // 512MB
__device__ __align__(16) uint2         g_Wxp[32u*64u*16u*32u];           // 8MB  [cn][kt][nt][lane]
__device__ __align__(16) uint2         g_Whp[128u*64u*4u*32u];           // 8MB  [ct][kt][g][lane]
__device__ float                       g_b4[NCOLS];
__device__ __align__(16) __nv_bfloat16 g_h[2][B_*H_];                    // ping-pong h (bf16)
__device__ __align__(16) float         g_c[B_*H_];                       // cell state fp32
__device__ __align__(16) float         g_hT[B_*H_];                      // final h fp32

// ---------------- small PTX helpers ----------------
__device__ __forceinline__ void cpa16(uint32_t saddr, const void* gptr) {
    asm volatile("cp.async.cg.shared.global [%0], [%1], 16;" :: "r"(saddr), "l"(gptr));
}
__device__ __forceinline__ void cpa_commit() { asm volatile("cp.async.commit_group;"); }
__device__ __forceinline__ void cpa_wait0()  { asm volatile("cp.async.wait_group 0;"); }
__device__ __forceinline__ void cpa_wait1()  { asm volatile("cp.async.wait_group 1;"); }
__device__ __forceinline__ void cpa_wait2()  { asm volatile("cp.async.wait_group 2;"); }

__device__ __forceinline__ void ldsm_x4(uint32_t& r0, uint32_t& r1, uint32_t& r2, uint32_t& r3,
                                        uint32_t saddr) {
    asm volatile("ldmatrix.sync.aligned.m8n8.x4.shared.b16 {%0,%1,%2,%3}, [%4];"
                 : "=r"(r0), "=r"(r1), "=r"(r2), "=r"(r3) : "r"(saddr));
}
__device__ __forceinline__ void mma16816(float* d, const uint32_t* a, const uint2 b) {
    asm volatile("mma.sync.aligned.m16n8k16.row.col.f32.bf16.bf16.f32 "
                 "{%0,%1,%2,%3}, {%4,%5,%6,%7}, {%8,%9}, {%0,%1,%2,%3};"
                 : "+f"(d[0]), "+f"(d[1]), "+f"(d[2]), "+f"(d[3])
                 : "r"(a[0]), "r"(a[1]), "r"(a[2]), "r"(a[3]), "r"(b.x), "r"(b.y));
}
__device__ __forceinline__ uint32_t s2u(const void* p) {
    return (uint32_t)__cvta_generic_to_shared(p);
}
__device__ __forceinline__ uint32_t swz(uint32_t byte) {   // 128B swizzle
    return byte ^ ((byte >> 3) & 0x70u);
}
__device__ __forceinline__ float fast_sigmoid(float x) {
    return 1.f / (1.f + __expf(-x));
}
__device__ __forceinline__ float fast_tanh(float x) {
    float e = __expf(-2.f * fabsf(x));
    float t = (1.f - e) / (1.f + e);
    return copysignf(t, x);
}

// ---------------- prep kernel 1: pack_wh + pack_b ----------
__global__ void __launch_bounds__(256) k_prep_w(const float* Wf, const float* bf,
                                                const float* Wi, const float* bi,
                                                const float* Wg, const float* bg,
                                                const float* Wo, const float* bo) {
    unsigned blk = blockIdx.x, tid = threadIdx.x;
    if (blk < 4096u) {
        unsigned id = blk * 256u + tid;       // pack Wh fragments
        unsigned lane = id & 31u, g = (id >> 5) & 3u, kt = (id >> 7) & 63u, ct = id >> 13;
        unsigned j = ct * 8u + (lane >> 2);
        unsigned k0 = kt * 16u + (lane & 3u) * 2u;
        const float* W = (g == 0) ? Wf : (g == 1) ? Wi : (g == 2) ? Wg : Wo;
        const float* base = W + (size_t)j * (D_ + H_) + D_ + k0;
        __nv_bfloat162 p0 = __floats2bfloat162_rn(base[0], base[1]);
        __nv_bfloat162 p1 = __floats2bfloat162_rn(base[8], base[9]);
        uint2 out;
        out.x = *reinterpret_cast<uint32_t*>(&p0);
        out.y = *reinterpret_cast<uint32_t*>(&p1);
        g_Whp[id] = out;
    } else {
        for (int r = 0; r < 16; r++) {
            unsigned i = tid * 16u + r;
            unsigned g = i >> 10, j = i & 1023u;
            const float* b = (g == 0) ? bf : (g == 1) ? bi : (g == 2) ? bg : bo;
            g_b4[i] = b[j];
        }
    }
}

// ---------------- prep kernel 2: cvt_x + pack_wx ----------------
__global__ void __launch_bounds__(512) k_prep_x(const float* __restrict__ x,
                                                const float* Wf, const float* Wi,
                                                const float* Wg, const float* Wo) {
    unsigned blk = blockIdx.x, tid = threadIdx.x;
    if (blk < 16384u) {
        size_t idx = (size_t)blk * 512 + tid;   // 8388608 float4s
        float4 v = reinterpret_cast<const float4*>(x)[idx];
        __nv_bfloat162* dst = reinterpret_cast<__nv_bfloat162*>(g_xbf);
        dst[idx * 2 + 0] = __floats2bfloat162_rn(v.x, v.y);
        dst[idx * 2 + 1] = __floats2bfloat162_rn(v.z, v.w);
    } else {
        unsigned id = (blk - 16384u) * 512u + tid;   // 1048576 ids
        unsigned lane = id & 31u, nt = (id >> 5) & 15u, kt = (id >> 9) & 63u, cn = id >> 15;
        unsigned c = cn * 128u + nt * 8u + (lane >> 2);
        unsigned g = c >> 10, j = c & 1023u;
        unsigned k0 = kt * 16u + (lane & 3u) * 2u;
        const float* W = (g == 0) ? Wf : (g == 1) ? Wi : (g == 2) ? Wg : Wo;
        const float* base = W + (size_t)j * (D_ + H_) + k0;
        __nv_bfloat162 p0 = __floats2bfloat162_rn(base[0], base[1]);
        __nv_bfloat162 p1 = __floats2bfloat162_rn(base[8], base[9]);
        uint2 out;
        out.x = *reinterpret_cast<uint32_t*>(&p0);
        out.y = *reinterpret_cast<uint32_t*>(&p1);
        g_Wxp[id] = out;
    }
}

// ---------------- Phase A: Zx = xbf @ Wx4^T + b4 ----------------
__global__ void __launch_bounds__(256) k_gemmA() {
    extern __shared__ char sm[];
    const int tid = threadIdx.x, lane = tid & 31, w = tid >> 5;
    const int wm = w >> 2, wn = w & 3;
    const int cn = blockIdx.x;           // 0..31
    const int m0 = blockIdx.y * 128;     // 0..32640

    float acc[4][4][4];
#pragma unroll
    for (int a = 0; a < 4; a++)
#pragma unroll
        for (int b = 0; b < 4; b++)
#pragma unroll
            for (int c = 0; c < 4; c++) acc[a][b][c] = 0.f;

    auto load_chunk = [&](int kc) {
        int st = kc % 3;
        char* A = sm + (size_t)st * 32768;
        uint4* bdst = reinterpret_cast<uint4*>(sm + (size_t)st * 32768 + 16384);
#pragma unroll
        for (int i = 0; i < 4; i++) {
            int idx = tid + i * 256;
            int row = idx >> 3, seg = idx & 7;
            const void* src = &g_xbf[(size_t)(m0 + row) * D_ + kc * 64 + seg * 8];
            cpa16(s2u(A + swz(row * 128 + seg * 16)), src);
        }
        const uint4* bsrc = reinterpret_cast<const uint4*>(&g_Wxp[((size_t)cn * 64 + kc * 4) * 16 * 32]);
#pragma unroll
        for (int i = 0; i < 4; i++) {
            int idx = tid + i * 256;
            cpa16(s2u(bdst + idx), bsrc + idx);
        }
        cpa_commit();
    };

    load_chunk(0);
    load_chunk(1);
    for (int kc = 0; kc < 16; kc++) {
        if (kc < 15) cpa_wait1(); else cpa_wait0();
        __syncthreads();
        int st = kc % 3;
        char* A = sm + (size_t)st * 32768;
        uint2* Bsm = reinterpret_cast<uint2*>(sm + (size_t)st * 32768 + 16384);
#pragma unroll
        for (int ktl = 0; ktl < 4; ktl++) {
            uint32_t afr[4][4];
#pragma unroll
            for (int mt = 0; mt < 4; mt++) {
                int r = wm * 64 + mt * 16 + (lane & 15);
                int ch = ktl * 16 + ((lane >> 4) << 3);
                ldsm_x4(afr[mt][0], afr[mt][1], afr[mt][2], afr[mt][3],
                        s2u(A + swz(r * 128 + ch * 2)));
            }
            uint2 bfr[4];
#pragma unroll
            for (int nt = 0; nt < 4; nt++)
                bfr[nt] = Bsm[((ktl) * 16 + wn * 4 + nt) * 32 + lane];
#pragma unroll
            for (int mt = 0; mt < 4; mt++)
#pragma unroll
                for (int nt = 0; nt < 4; nt++)
                    mma16816(acc[mt][nt], afr[mt], bfr[nt]);
        }
        if (kc + 2 < 16) load_chunk(kc + 2);
    }
#pragma unroll
    for (int mt = 0; mt < 4; mt++) {
        int r0 = m0 + wm * 64 + mt * 16 + (lane >> 2);
#pragma unroll
        for (int nt = 0; nt < 4; nt++) {
            int c0 = cn * 128 + wn * 32 + nt * 8 + (lane & 3) * 2;
            float b0 = g_b4[c0], b1 = g_b4[c0 + 1];
            float2 v0 = make_float2(acc[mt][nt][0] + b0, acc[mt][nt][1] + b1);
            float2 v1 = make_float2(acc[mt][nt][2] + b0, acc[mt][nt][3] + b1);
            *reinterpret_cast<float2*>(&g_Zx[(size_t)r0 * NCOLS + c0]) = v0;
            *reinterpret_cast<float2*>(&g_Zx[(size_t)(r0 + 8) * NCOLS + c0]) = v1;
        }
    }
}

// ---------------- Phase B: one kernel per timestep (graph provides barrier) --
// 128 CTAs x 256 threads. CTA ct owns hidden units [ct*8, ct*8+8) x 4 gates
// x 128 batches. Wh slice (64KB) staged via cp.async first; Zx loaded as
// float4 (coalesced); h streamed through a 4-stage cp.async ring; c in g_c.
// smem: WhS 64KB + ring 64KB + zs 16KB = 144KB
__global__ void __launch_bounds__(256) k_step(int t) {
    extern __shared__ char sm[];
    uint2* WhS = reinterpret_cast<uint2*>(sm);                 // 64KB
    char*  As  = sm + 65536;                                    // 4 x 16KB ring
    float* zs  = reinterpret_cast<float*>(sm + 131072);         // 16KB
    const int ct = blockIdx.x;
    const int tid = threadIdx.x, lane = tid & 31, w = tid >> 5;
    const int wm = w >> 1, wn = w & 1;
    const bool last = (t == T_ - 1);
    const int bb = tid >> 1;              // batch row (2 threads per batch)
    const int jl = (tid & 1) * 4;         // 4 consecutive units per thread

    // issue Wh stage FIRST so it overlaps the Zx/c register loads
    if (t > 0) {
        const uint4* src = reinterpret_cast<const uint4*>(&g_Whp[(size_t)ct * 64 * 4 * 32]);
#pragma unroll
        for (int i = 0; i < 16; i++) {
            int idx = tid + i * 256;
            cpa16(s2u(reinterpret_cast<uint4*>(WhS) + idx), src + idx);
        }
        cpa_commit();
    }

    // Zx + c loads (coalesced float4)
    float zx[4][4];  // zx[i][g] for cells jl..jl+3
    float cst[4];
    {
        const float* zp = &g_Zx[(size_t)(t * B_ + bb) * NCOLS + ct * 8 + jl];
#pragma unroll
        for (int g = 0; g < 4; g++) {
            float4 v = __ldcs(reinterpret_cast<const float4*>(zp + g * 1024));
            zx[0][g] = v.x; zx[1][g] = v.y; zx[2][g] = v.z; zx[3][g] = v.w;
        }
        if (t > 0) {
            float4 cv = *reinterpret_cast<const float4*>(&g_c[(size_t)bb * H_ + ct * 8 + jl]);
            cst[0] = cv.x; cst[1] = cv.y; cst[2] = cv.z; cst[3] = cv.w;
        } else {
            cst[0] = cst[1] = cst[2] = cst[3] = 0.f;
        }
    }

    if (t > 0) {
        const __nv_bfloat16* hsrc = g_h[(t + 1) & 1];
        auto load_chunk = [&](int kc) {
            char* A = As + (size_t)(kc & 3) * 16384;
#pragma unroll
            for (int i = 0; i < 4; i++) {
                int idx = tid + i * 256;
                int row = idx >> 3, seg = idx & 7;
                const void* src = &hsrc[(size_t)row * H_ + kc * 64 + seg * 8];
                cpa16(s2u(A + swz(row * 128 + seg * 16)), src);
            }
            cpa_commit();
        };
        load_chunk(0);
        load_chunk(1);
        load_chunk(2);

        float acc[2][2][4];
#pragma unroll
        for (int a = 0; a < 2; a++)
#pragma unroll
            for (int b = 0; b < 2; b++)
#pragma unroll
                for (int c = 0; c < 4; c++) acc[a][b][c] = 0.f;

        for (int kc = 0; kc < 16; kc++) {
            // pending groups after wait must include h_kc: committed = 1(Wh)+min(kc+3,16)
            if (kc <= 13)      cpa_wait2();
            else if (kc == 14) cpa_wait1();
            else               cpa_wait0();
            __syncthreads();
            char* A = As + (size_t)(kc & 3) * 16384;
#pragma unroll
            for (int ktl = 0; ktl < 4; ktl++) {
                uint2 bfr[2];
#pragma unroll
                for (int nt = 0; nt < 2; nt++)
                    bfr[nt] = WhS[(((kc * 4 + ktl) * 4) + wn * 2 + nt) * 32 + lane];
#pragma unroll
                for (int mt = 0; mt < 2; mt++) {
                    int r = wm * 32 + mt * 16 + (lane & 15);
                    int ch = ktl * 16 + ((lane >> 4) << 3);
                    uint32_t afr[4];
                    ldsm_x4(afr[0], afr[1], afr[2], afr[3],
                            s2u(A + swz(r * 128 + ch * 2)));
                    mma16816(acc[mt][0], afr, bfr[0]);
                    mma16816(acc[mt][1], afr, bfr[1]);
                }
            }
            if (kc + 3 < 16) load_chunk(kc + 3);
        }
        // z exchange via smem
#pragma unroll
        for (int mt = 0; mt < 2; mt++) {
            int r = wm * 32 + mt * 16 + (lane >> 2);
#pragma unroll
            for (int nt = 0; nt < 2; nt++) {
                int cl = (wn * 2 + nt) * 8 + (lane & 3) * 2;
                zs[r * 32 + cl]           = acc[mt][nt][0];
                zs[r * 32 + cl + 1]       = acc[mt][nt][1];
                zs[(r + 8) * 32 + cl]     = acc[mt][nt][2];
                zs[(r + 8) * 32 + cl + 1] = acc[mt][nt][3];
            }
        }
        __syncthreads();
    }

    // gate math + h/c write (4 consecutive cells per thread; zs reads are LDS.128)
    __nv_bfloat16* hdst = g_h[t & 1];
    float hh[4], cn[4];
    float4 zi4, zf4, zg4, zo4;
    if (t > 0) {
        const float* zb = zs + bb * 32 + jl;
        zi4 = *reinterpret_cast<const float4*>(zb + 0);
        zf4 = *reinterpret_cast<const float4*>(zb + 8);
        zg4 = *reinterpret_cast<const float4*>(zb + 16);
        zo4 = *reinterpret_cast<const float4*>(zb + 24);
    } else {
        zi4 = zf4 = zg4 = zo4 = make_float4(0.f, 0.f, 0.f, 0.f);
    }
    const float* zia = &zi4.x;
    const float* zfa = &zf4.x;
    const float* zga = &zg4.x;
    const float* zoa = &zo4.x;
#pragma unroll
    for (int i = 0; i < 4; i++) {
        float zi = zx[i][0] + zia[i];
        float zf = zx[i][1] + zfa[i];
        float zg = zx[i][2] + zga[i];
        float zo = zx[i][3] + zoa[i];
        float it = fast_sigmoid(zi);
        float ft = fast_sigmoid(zf);
        float gt = fast_tanh(zg);
        float ot = fast_sigmoid(zo);
        cn[i] = ft * cst[i] + it * gt;
        hh[i] = ot * fast_tanh(cn[i]);
    }
    if (!last) {
        __nv_bfloat162 h01 = __floats2bfloat162_rn(hh[0], hh[1]);
        __nv_bfloat162 h23 = __floats2bfloat162_rn(hh[2], hh[3]);
        uint2 hp;
        hp.x = *reinterpret_cast<uint32_t*>(&h01);
        hp.y = *reinterpret_cast<uint32_t*>(&h23);
        *reinterpret_cast<uint2*>(&hdst[(size_t)bb * H_ + ct * 8 + jl]) = hp;
        *reinterpret_cast<float4*>(&g_c[(size_t)bb * H_ + ct * 8 + jl]) =
            make_float4(cn[0], cn[1], cn[2], cn[3]);
    } else {
        *reinterpret_cast<float4*>(&g_hT[(size_t)bb * H_ + ct * 8 + jl]) =
            make_float4(hh[0], hh[1], hh[2], hh[3]);
    }
}

// ---------------- Phase C: logits + log_softmax ----------------
__global__ void __launch_bounds__(256) k_logits(const float* __restrict__ Wout,
                                                const float* __restrict__ bout,
                                                float* __restrict__ out) {
    __shared__ float hs[1024];
    __shared__ float ls[1024];
    __shared__ float red[16];
    const int b = blockIdx.x, tid = threadIdx.x, lane = tid & 31, w = tid >> 5;
    for (int i = tid; i < 1024; i += 256) hs[i] = g_hT[(size_t)b * H_ + i];
    __syncthreads();
    for (int k = 0; k < 4; k++) {
        int o = tid + k * 256;
        const float4* wr = reinterpret_cast<const float4*>(Wout + (size_t)o * H_);
        float s = 0.f;
#pragma unroll 4
        for (int h4 = 0; h4 < 256; h4++) {
            float4 wv = wr[h4];
            s += hs[h4 * 4 + 0] * wv.x + hs[h4 * 4 + 1] * wv.y +
                 hs[h4 * 4 + 2] * wv.z + hs[h4 * 4 + 3] * wv.w;
        }
        ls[o] = s + bout[o];
    }
    __syncthreads();
    float lm = -1e30f;
    for (int i = tid; i < 1024; i += 256) lm = fmaxf(lm, ls[i]);
#pragma unroll
    for (int off = 16; off; off >>= 1) lm = fmaxf(lm, __shfl_xor_sync(0xffffffffu, lm, off));
    if (lane == 0) red[w] = lm;
    __syncthreads();
    float m = red[0];
#pragma unroll
    for (int j = 1; j < 8; j++) m = fmaxf(m, red[j]);
    float se = 0.f;
    for (int i = tid; i < 1024; i += 256) se += expf(ls[i] - m);
#pragma unroll
    for (int off = 16; off; off >>= 1) se += __shfl_xor_sync(0xffffffffu, se, off);
    if (lane == 0) red[8 + w] = se;
    __syncthreads();
    float tot = 0.f;
#pragma unroll
    for (int j = 0; j < 8; j++) tot += red[8 + j];
    float lse = logf(tot);
    for (int i = tid; i < 1024; i += 256)
        out[(size_t)b * O_ + i] = ls[i] - m - lse;
}

// ---------------- launch ----------------
extern "C" void kernel_launch(void* const* d_in, const int* in_sizes, int n_in,
                              void* d_out, int out_size) {
    const float* x    = (const float*)d_in[0];
    const float* Wf   = (const float*)d_in[1];
    const float* bf   = (const float*)d_in[2];
    const float* Wi   = (const float*)d_in[3];
    const float* bi   = (const float*)d_in[4];
    const float* Wg   = (const float*)d_in[5];
    const float* bg   = (const float*)d_in[6];
    const float* Wo   = (const float*)d_in[7];
    const float* bo   = (const float*)d_in[8];
    const float* Wout = (const float*)d_in[9];
    const float* bout = (const float*)d_in[10];
    float* out = (float*)d_out;

    cudaFuncSetAttribute(k_gemmA, cudaFuncAttributeMaxDynamicSharedMemorySize, 98304);
    cudaFuncSetAttribute(k_step,  cudaFuncAttributeMaxDynamicSharedMemorySize, 147456);

    k_prep_w<<<4097, 256>>>(Wf, bf, Wi, bi, Wg, bg, Wo, bo);
    k_prep_x<<<18432, 512>>>(x, Wf, Wi, Wg, Wo);
    dim3 gA(32, 256);
    k_gemmA<<<gA, 256, 98304>>>();
    for (int t = 0; t < T_; t++)
        k_step<<<128, 256, 147456>>>(t);
    k_logits<<<B_, 256>>>(Wout, bout, out);
}